// round 2
// baseline (speedup 1.0000x reference)
#include <cuda_runtime.h>
#include <cstdint>

// ---------------- problem constants ----------------
#define N_ATOMS   500000
#define N_PER_DEG 125000
#define NODE      128
#define EDGE      64
#define OUT_C     128
#define TILE_M    128
#define N_TILES   977          // ceil(125000/128)
#define BN_EPS    1e-5f

// ---------------- SMEM layout (dynamic) ----------------
// [0, 1024):            s_sum[128], s_sq[128]
// [1024, 171008):       Wsm  uint32[128][332]   (W as tf32, [n][k], stride 332)
// [171008, 207872):     Abuf uint32[2][128][36] (A chunk tf32, stride 36)
#define W_STRIDE  332
#define A_STRIDE  36
#define OFF_STATS 0
#define OFF_W     1024
#define OFF_A     171008
#define A_BUFSZ   (128 * A_STRIDE)            // words
#define SMEM_TOTAL 207872

__device__ __forceinline__ uint32_t f2tf32(float f) {
    uint32_t r;
    asm("cvt.rna.tf32.f32 %0, %1;" : "=r"(r) : "f"(f));
    return r;
}

__device__ __forceinline__ void mma_m16n8k8(float d[4], const uint32_t a[4],
                                            uint32_t b0, uint32_t b1) {
    asm volatile(
        "mma.sync.aligned.m16n8k8.row.col.f32.tf32.tf32.f32 "
        "{%0,%1,%2,%3}, {%4,%5,%6,%7}, {%8,%9}, {%0,%1,%2,%3};"
        : "+f"(d[0]), "+f"(d[1]), "+f"(d[2]), "+f"(d[3])
        : "r"(a[0]), "r"(a[1]), "r"(a[2]), "r"(a[3]), "r"(b0), "r"(b1));
}

// ---------------- BN scratch (device globals: no allocation allowed) ----------------
__device__ float g_sum[OUT_C];
__device__ float g_sumsq[OUT_C];
__device__ float g_mean[OUT_C];
__device__ float g_istd[OUT_C];

// ---------------- fused gather + tf32 GEMM + bias + stats, per degree ----------------
// 256 threads = 8 warps. Warp tile: 32(M) x 64(N). warp_m = wid&3, warp_n = wid>>2.
// K = 320 processed in 10 chunks of 32:
//   chunks 0-3: atom-neighbor sum cols [c*32,+32)
//   chunks 4-5: bond-neighbor sum cols [(c-4)*32,+32)
//   chunks 6-9: self atom row cols [(c-6)*32,+32)
template <int DEG>
__global__ __launch_bounds__(256, 1)
void gconv_kernel(const float* __restrict__ atom_repr,
                  const float* __restrict__ bond_repr,
                  const int*   __restrict__ aidx,
                  const int*   __restrict__ bidx,
                  const float* __restrict__ Wd,
                  const float* __restrict__ Wself,
                  const float* __restrict__ bias,
                  float*       __restrict__ out,
                  int deg_base) {
    extern __shared__ char smem[];
    float*    s_sum = (float*)(smem + OFF_STATS);
    float*    s_sq  = s_sum + OUT_C;
    uint32_t* Wsm   = (uint32_t*)(smem + OFF_W);
    uint32_t* Ab    = (uint32_t*)(smem + OFF_A);

    const int tid  = threadIdx.x;
    const int wid  = tid >> 5;
    const int lane = tid & 31;
    const int warp_m = wid & 3;
    const int warp_n = wid >> 2;
    const int tile_base = blockIdx.x * TILE_M;

    if (tid < OUT_C) { s_sum[tid] = 0.f; s_sq[tid] = 0.f; }

    // ---- load W = [Wd | Wself] into SMEM as tf32, layout Wsm[n][k] ----
    for (int e4 = tid; e4 < OUT_C * 80; e4 += 256) {
        int n  = e4 / 80;
        int k4 = (e4 - n * 80) * 4;
        const float* src = (k4 < 192) ? (Wd + n * 192 + k4) : (Wself + n * 128 + (k4 - 192));
        float4 v = __ldg((const float4*)src);
        uint4 u = make_uint4(f2tf32(v.x), f2tf32(v.y), f2tf32(v.z), f2tf32(v.w));
        *(uint4*)(Wsm + n * W_STRIDE + k4) = u;
    }

    // ---- gather setup ----
    const int r    = tid >> 1;            // row 0..127
    const int half = tid & 1;             // 16-col half
    const int row_in_deg = tile_base + r;
    const bool gvalid = row_in_deg < N_PER_DEG;
    const int rid = gvalid ? row_in_deg : (N_PER_DEG - 1);

    int ai[DEG], bi[DEG];
#pragma unroll
    for (int j = 0; j < DEG; j++) {
        ai[j] = aidx[rid * DEG + j];
        bi[j] = bidx[rid * DEG + j];
    }
    const int selfrow = deg_base + rid;

    float4 vr[DEG][4];
    float4 vs[4];   // self chunk regs

    auto load_next = [&](int c) {
        if (c < 4) {
            int co = c * 32 + half * 16;
#pragma unroll
            for (int j = 0; j < DEG; j++) {
                const float4* p = (const float4*)(atom_repr + (size_t)ai[j] * NODE + co);
#pragma unroll
                for (int i = 0; i < 4; i++) vr[j][i] = __ldg(p + i);
            }
        } else if (c < 6) {
            int co = (c - 4) * 32 + half * 16;
#pragma unroll
            for (int j = 0; j < DEG; j++) {
                const float4* p = (const float4*)(bond_repr + (size_t)bi[j] * EDGE + co);
#pragma unroll
                for (int i = 0; i < 4; i++) vr[j][i] = __ldg(p + i);
            }
        } else {
            int co = (c - 6) * 32 + half * 16;
            const float4* p = (const float4*)(atom_repr + (size_t)selfrow * NODE + co);
#pragma unroll
            for (int i = 0; i < 4; i++) vs[i] = __ldg(p + i);
        }
    };

    auto store_cur = [&](int c, uint32_t* buf) {
        float4 s[4];
        if (c < 6) {
#pragma unroll
            for (int i = 0; i < 4; i++) s[i] = vr[0][i];
#pragma unroll
            for (int j = 1; j < DEG; j++)
#pragma unroll
                for (int i = 0; i < 4; i++) {
                    s[i].x += vr[j][i].x; s[i].y += vr[j][i].y;
                    s[i].z += vr[j][i].z; s[i].w += vr[j][i].w;
                }
        } else {
#pragma unroll
            for (int i = 0; i < 4; i++) s[i] = vs[i];
        }
        if (!gvalid) {
#pragma unroll
            for (int i = 0; i < 4; i++) s[i] = make_float4(0.f, 0.f, 0.f, 0.f);
        }
        uint32_t* dst = buf + r * A_STRIDE + half * 16;
#pragma unroll
        for (int i = 0; i < 4; i++) {
            *(uint4*)(dst + i * 4) =
                make_uint4(f2tf32(s[i].x), f2tf32(s[i].y), f2tf32(s[i].z), f2tf32(s[i].w));
        }
    };

    float acc[2][8][4];
#pragma unroll
    for (int mi = 0; mi < 2; mi++)
#pragma unroll
        for (int nb = 0; nb < 8; nb++)
#pragma unroll
            for (int i = 0; i < 4; i++) acc[mi][nb][i] = 0.f;

    // ---- pipeline: prefetch chunk0, then (LDG next | MMA cur | STS next | sync) ----
    load_next(0);
    store_cur(0, Ab);
    __syncthreads();

#pragma unroll
    for (int c = 0; c < 10; c++) {
        if (c < 9) load_next(c + 1);

        const uint32_t* buf = Ab + (c & 1) * A_BUFSZ;
        const int kbase = c * 32;
#pragma unroll
        for (int s = 0; s < 4; s++) {
            const int kk = s * 8 + (lane & 3);
            uint32_t a[2][4];
#pragma unroll
            for (int mi = 0; mi < 2; mi++) {
                int row = warp_m * 32 + mi * 16 + (lane >> 2);
                a[mi][0] = buf[row * A_STRIDE + kk];
                a[mi][1] = buf[(row + 8) * A_STRIDE + kk];
                a[mi][2] = buf[row * A_STRIDE + kk + 4];
                a[mi][3] = buf[(row + 8) * A_STRIDE + kk + 4];
            }
#pragma unroll
            for (int nb = 0; nb < 8; nb++) {
                int n = warp_n * 64 + nb * 8 + (lane >> 2);
                uint32_t b0 = Wsm[n * W_STRIDE + kbase + kk];
                uint32_t b1 = Wsm[n * W_STRIDE + kbase + kk + 4];
                mma_m16n8k8(acc[0][nb], a[0], b0, b1);
                mma_m16n8k8(acc[1][nb], a[1], b0, b1);
            }
        }

        if (c < 9) store_cur(c + 1, Ab + ((c + 1) & 1) * A_BUFSZ);
        __syncthreads();
    }

    // ---- epilogue: bias + store + fused BN partial stats ----
#pragma unroll
    for (int nb = 0; nb < 8; nb++) {
        const int col0 = warp_n * 64 + nb * 8 + (lane & 3) * 2;
        const float bv0 = __ldg(bias + col0);
        const float bv1 = __ldg(bias + col0 + 1);
        float ps0 = 0.f, ps1 = 0.f, pq0 = 0.f, pq1 = 0.f;
#pragma unroll
        for (int mi = 0; mi < 2; mi++) {
            int gr0 = tile_base + warp_m * 32 + mi * 16 + (lane >> 2);
            float x00 = acc[mi][nb][0] + bv0;
            float x01 = acc[mi][nb][1] + bv1;
            float x10 = acc[mi][nb][2] + bv0;
            float x11 = acc[mi][nb][3] + bv1;
            if (gr0 < N_PER_DEG) {
                float2 v = make_float2(x00, x01);
                *(float2*)(out + (size_t)(deg_base + gr0) * OUT_C + col0) = v;
                ps0 += x00; ps1 += x01; pq0 += x00 * x00; pq1 += x01 * x01;
            }
            if (gr0 + 8 < N_PER_DEG) {
                float2 v = make_float2(x10, x11);
                *(float2*)(out + (size_t)(deg_base + gr0 + 8) * OUT_C + col0) = v;
                ps0 += x10; ps1 += x11; pq0 += x10 * x10; pq1 += x11 * x11;
            }
        }
#pragma unroll
        for (int m = 4; m < 32; m <<= 1) {
            ps0 += __shfl_xor_sync(0xffffffffu, ps0, m);
            ps1 += __shfl_xor_sync(0xffffffffu, ps1, m);
            pq0 += __shfl_xor_sync(0xffffffffu, pq0, m);
            pq1 += __shfl_xor_sync(0xffffffffu, pq1, m);
        }
        if ((lane >> 2) == 0) {
            atomicAdd(&s_sum[col0], ps0);
            atomicAdd(&s_sum[col0 + 1], ps1);
            atomicAdd(&s_sq[col0], pq0);
            atomicAdd(&s_sq[col0 + 1], pq1);
        }
    }

    __syncthreads();
    if (tid < OUT_C) {
        atomicAdd(&g_sum[tid], s_sum[tid]);
        atomicAdd(&g_sumsq[tid], s_sq[tid]);
    }
}

// ---------------- K0: zero stats ----------------
__global__ void zero_stats_kernel() {
    if (threadIdx.x < OUT_C) { g_sum[threadIdx.x] = 0.f; g_sumsq[threadIdx.x] = 0.f; }
}

// ---------------- K3: finalize mean / inv-std ----------------
__global__ void finalize_stats_kernel() {
    int c = threadIdx.x;
    if (c < OUT_C) {
        float mean = g_sum[c] * (1.0f / N_ATOMS);
        float var = g_sumsq[c] * (1.0f / N_ATOMS) - mean * mean;
        g_mean[c] = mean;
        g_istd[c] = rsqrtf(var + BN_EPS);
    }
}

// ---------------- K4: BN normalize + ReLU in place ----------------
__global__ void bn_relu_kernel(float4* __restrict__ x, int n4) {
    int t = blockIdx.x * blockDim.x + threadIdx.x;
    int stride = gridDim.x * blockDim.x;   // multiple of 32
    int c = (t & 31) * 4;
    float m0 = g_mean[c + 0], m1 = g_mean[c + 1], m2 = g_mean[c + 2], m3 = g_mean[c + 3];
    float i0 = g_istd[c + 0], i1 = g_istd[c + 1], i2 = g_istd[c + 2], i3 = g_istd[c + 3];
    for (int i = t; i < n4; i += stride) {
        float4 v = x[i];
        v.x = fmaxf((v.x - m0) * i0, 0.f);
        v.y = fmaxf((v.y - m1) * i1, 0.f);
        v.z = fmaxf((v.z - m2) * i2, 0.f);
        v.w = fmaxf((v.w - m3) * i3, 0.f);
        x[i] = v;
    }
}

// ---------------- launch ----------------
extern "C" void kernel_launch(void* const* d_in, const int* in_sizes, int n_in,
                              void* d_out, int out_size) {
    (void)n_in; (void)out_size;

    const float* atom_repr = (const float*)d_in[0];
    const float* bond_repr = (const float*)d_in[1];
    const int* aidx[4];
    const int* bidx[4];
    const float* W[4];
    const float* Wself;
    const float* bias;

    if (in_sizes[4] == OUT_C * (NODE + EDGE)) {
        // dict / interleaved order: aidx_d, bidx_d, W_d per degree
        for (int d = 0; d < 4; d++) {
            aidx[d] = (const int*)d_in[2 + 3 * d];
            bidx[d] = (const int*)d_in[3 + 3 * d];
            W[d]    = (const float*)d_in[4 + 3 * d];
        }
    } else {
        // signature order: aidx1..4, bidx1..4, W1..4
        for (int d = 0; d < 4; d++) {
            aidx[d] = (const int*)d_in[2 + d];
            bidx[d] = (const int*)d_in[6 + d];
            W[d]    = (const float*)d_in[10 + d];
        }
    }
    Wself = (const float*)d_in[14];
    bias  = (const float*)d_in[15];
    float* out = (float*)d_out;

    cudaFuncSetAttribute(gconv_kernel<1>, cudaFuncAttributeMaxDynamicSharedMemorySize, SMEM_TOTAL);
    cudaFuncSetAttribute(gconv_kernel<2>, cudaFuncAttributeMaxDynamicSharedMemorySize, SMEM_TOTAL);
    cudaFuncSetAttribute(gconv_kernel<3>, cudaFuncAttributeMaxDynamicSharedMemorySize, SMEM_TOTAL);
    cudaFuncSetAttribute(gconv_kernel<4>, cudaFuncAttributeMaxDynamicSharedMemorySize, SMEM_TOTAL);

    zero_stats_kernel<<<1, 128>>>();
    gconv_kernel<1><<<N_TILES, 256, SMEM_TOTAL>>>(atom_repr, bond_repr, aidx[0], bidx[0], W[0], Wself, bias, out, 0 * N_PER_DEG);
    gconv_kernel<2><<<N_TILES, 256, SMEM_TOTAL>>>(atom_repr, bond_repr, aidx[1], bidx[1], W[1], Wself, bias, out, 1 * N_PER_DEG);
    gconv_kernel<3><<<N_TILES, 256, SMEM_TOTAL>>>(atom_repr, bond_repr, aidx[2], bidx[2], W[2], Wself, bias, out, 2 * N_PER_DEG);
    gconv_kernel<4><<<N_TILES, 256, SMEM_TOTAL>>>(atom_repr, bond_repr, aidx[3], bidx[3], W[3], Wself, bias, out, 3 * N_PER_DEG);

    finalize_stats_kernel<<<1, 128>>>();
    const int n4 = (N_ATOMS * OUT_C) / 4;
    bn_relu_kernel<<<2960, 256>>>((float4*)out, n4);
}

// round 3
// speedup vs baseline: 1.1330x; 1.1330x over previous
#include <cuda_runtime.h>
#include <cstdint>

// ---------------- problem constants ----------------
#define N_ATOMS   500000
#define N_PER_DEG 125000
#define NODE      128
#define EDGE      64
#define OUT_C     128
#define TILE_M    128
#define N_TILES   977          // ceil(125000/128)
#define BN_EPS    1e-5f

// ---------------- SMEM layout (dynamic) ----------------
// [0, 1024):            s_sum[128], s_sq[128]
// [1024, 171008):       Wsm  uint32[128][332]   (W as tf32, [n][k], stride 332)
// [171008, 207872):     Abuf uint32[2][128][36] (A chunk tf32, stride 36)
#define W_STRIDE  332
#define A_STRIDE  36
#define OFF_STATS 0
#define OFF_W     1024
#define OFF_A     171008
#define A_BUFSZ   (128 * A_STRIDE)            // words
#define SMEM_TOTAL 207872

__device__ __forceinline__ uint32_t f2tf32(float f) {
    uint32_t r;
    asm("cvt.rna.tf32.f32 %0, %1;" : "=r"(r) : "f"(f));
    return r;
}

__device__ __forceinline__ void mma_m16n8k8(float d[4], const uint32_t a[4],
                                            uint32_t b0, uint32_t b1) {
    asm volatile(
        "mma.sync.aligned.m16n8k8.row.col.f32.tf32.tf32.f32 "
        "{%0,%1,%2,%3}, {%4,%5,%6,%7}, {%8,%9}, {%0,%1,%2,%3};"
        : "+f"(d[0]), "+f"(d[1]), "+f"(d[2]), "+f"(d[3])
        : "r"(a[0]), "r"(a[1]), "r"(a[2]), "r"(a[3]), "r"(b0), "r"(b1));
}

// ---------------- BN scratch (device globals: no allocation allowed) ----------------
__device__ float g_sum[OUT_C];
__device__ float g_sumsq[OUT_C];
__device__ float g_mean[OUT_C];
__device__ float g_istd[OUT_C];

// ---------------- fused gather + tf32 GEMM + bias + stats body ----------------
// 512 threads = 16 warps. Warp tile: 32(M) x 32(N). warp_m = wid&3, warp_n = wid>>2.
// K = 320 in 10 chunks of 32:
//   chunks 0-3: atom-neighbor sum; chunks 4-5: bond-neighbor sum; chunks 6-9: self row.
template <int DEG>
__device__ __forceinline__
void gconv_body(const float* __restrict__ atom_repr,
                const float* __restrict__ bond_repr,
                const int*   __restrict__ aidx,
                const int*   __restrict__ bidx,
                const float* __restrict__ Wd,
                const float* __restrict__ Wself,
                const float* __restrict__ bias,
                float*       __restrict__ out,
                int deg_base, int tile_base, char* smem) {
    float*    s_sum = (float*)(smem + OFF_STATS);
    float*    s_sq  = s_sum + OUT_C;
    uint32_t* Wsm   = (uint32_t*)(smem + OFF_W);
    uint32_t* Ab    = (uint32_t*)(smem + OFF_A);

    const int tid  = threadIdx.x;
    const int wid  = tid >> 5;
    const int lane = tid & 31;
    const int warp_m = wid & 3;
    const int warp_n = wid >> 2;

    if (tid < OUT_C) { s_sum[tid] = 0.f; s_sq[tid] = 0.f; }

    // ---- load W = [Wd | Wself] into SMEM as tf32, layout Wsm[n][k] ----
    for (int e4 = tid; e4 < OUT_C * 80; e4 += 512) {
        int n  = e4 / 80;
        int k4 = (e4 - n * 80) * 4;
        const float* src = (k4 < 192) ? (Wd + n * 192 + k4) : (Wself + n * 128 + (k4 - 192));
        float4 v = __ldg((const float4*)src);
        uint4 u = make_uint4(f2tf32(v.x), f2tf32(v.y), f2tf32(v.z), f2tf32(v.w));
        *(uint4*)(Wsm + n * W_STRIDE + k4) = u;
    }

    // ---- gather setup: thread -> (row r, 8-col quarter q) ----
    const int r = tid >> 2;               // row 0..127
    const int q = tid & 3;                // col quarter
    const int row_in_deg = tile_base + r;
    const bool gvalid = row_in_deg < N_PER_DEG;
    const int rid = gvalid ? row_in_deg : (N_PER_DEG - 1);

    int ai[DEG], bi[DEG];
#pragma unroll
    for (int j = 0; j < DEG; j++) {
        ai[j] = aidx[rid * DEG + j];
        bi[j] = bidx[rid * DEG + j];
    }
    const int selfrow = deg_base + rid;

    float4 vr[DEG][2];

    auto load_next = [&](int c) {
        if (c < 4) {
            int co = c * 32 + q * 8;
#pragma unroll
            for (int j = 0; j < DEG; j++) {
                const float4* p = (const float4*)(atom_repr + (size_t)ai[j] * NODE + co);
                vr[j][0] = __ldg(p);
                vr[j][1] = __ldg(p + 1);
            }
        } else if (c < 6) {
            int co = (c - 4) * 32 + q * 8;
#pragma unroll
            for (int j = 0; j < DEG; j++) {
                const float4* p = (const float4*)(bond_repr + (size_t)bi[j] * EDGE + co);
                vr[j][0] = __ldg(p);
                vr[j][1] = __ldg(p + 1);
            }
        } else {
            int co = (c - 6) * 32 + q * 8;
            const float4* p = (const float4*)(atom_repr + (size_t)selfrow * NODE + co);
            vr[0][0] = __ldg(p);
            vr[0][1] = __ldg(p + 1);
        }
    };

    auto store_cur = [&](int c, uint32_t* buf) {
        float4 s0 = vr[0][0], s1 = vr[0][1];
        if (c < 6) {
#pragma unroll
            for (int j = 1; j < DEG; j++) {
                s0.x += vr[j][0].x; s0.y += vr[j][0].y; s0.z += vr[j][0].z; s0.w += vr[j][0].w;
                s1.x += vr[j][1].x; s1.y += vr[j][1].y; s1.z += vr[j][1].z; s1.w += vr[j][1].w;
            }
        }
        if (!gvalid) {
            s0 = make_float4(0.f, 0.f, 0.f, 0.f);
            s1 = make_float4(0.f, 0.f, 0.f, 0.f);
        }
        uint32_t* dst = buf + r * A_STRIDE + q * 8;
        *(uint4*)dst       = make_uint4(f2tf32(s0.x), f2tf32(s0.y), f2tf32(s0.z), f2tf32(s0.w));
        *(uint4*)(dst + 4) = make_uint4(f2tf32(s1.x), f2tf32(s1.y), f2tf32(s1.z), f2tf32(s1.w));
    };

    float acc[2][4][4];
#pragma unroll
    for (int mi = 0; mi < 2; mi++)
#pragma unroll
        for (int nb = 0; nb < 4; nb++)
#pragma unroll
            for (int i = 0; i < 4; i++) acc[mi][nb][i] = 0.f;

    // ---- pipeline: prefetch chunk0, then (LDG next | MMA cur | STS next | sync) ----
    load_next(0);
    store_cur(0, Ab);
    __syncthreads();

#pragma unroll
    for (int c = 0; c < 10; c++) {
        if (c < 9) load_next(c + 1);

        const uint32_t* buf = Ab + (c & 1) * A_BUFSZ;
        const int kbase = c * 32;
#pragma unroll
        for (int s = 0; s < 4; s++) {
            const int kk = s * 8 + (lane & 3);
            uint32_t a[2][4];
#pragma unroll
            for (int mi = 0; mi < 2; mi++) {
                int row = warp_m * 32 + mi * 16 + (lane >> 2);
                a[mi][0] = buf[row * A_STRIDE + kk];
                a[mi][1] = buf[(row + 8) * A_STRIDE + kk];
                a[mi][2] = buf[row * A_STRIDE + kk + 4];
                a[mi][3] = buf[(row + 8) * A_STRIDE + kk + 4];
            }
#pragma unroll
            for (int nb = 0; nb < 4; nb++) {
                int n = warp_n * 32 + nb * 8 + (lane >> 2);
                uint32_t b0 = Wsm[n * W_STRIDE + kbase + kk];
                uint32_t b1 = Wsm[n * W_STRIDE + kbase + kk + 4];
                mma_m16n8k8(acc[0][nb], a[0], b0, b1);
                mma_m16n8k8(acc[1][nb], a[1], b0, b1);
            }
        }

        if (c < 9) store_cur(c + 1, Ab + ((c + 1) & 1) * A_BUFSZ);
        __syncthreads();
    }

    // ---- epilogue: bias + store + fused BN partial stats ----
#pragma unroll
    for (int nb = 0; nb < 4; nb++) {
        const int col0 = warp_n * 32 + nb * 8 + (lane & 3) * 2;
        const float bv0 = __ldg(bias + col0);
        const float bv1 = __ldg(bias + col0 + 1);
        float ps0 = 0.f, ps1 = 0.f, pq0 = 0.f, pq1 = 0.f;
#pragma unroll
        for (int mi = 0; mi < 2; mi++) {
            int gr0 = tile_base + warp_m * 32 + mi * 16 + (lane >> 2);
            float x00 = acc[mi][nb][0] + bv0;
            float x01 = acc[mi][nb][1] + bv1;
            float x10 = acc[mi][nb][2] + bv0;
            float x11 = acc[mi][nb][3] + bv1;
            if (gr0 < N_PER_DEG) {
                *(float2*)(out + (size_t)(deg_base + gr0) * OUT_C + col0) = make_float2(x00, x01);
                ps0 += x00; ps1 += x01; pq0 += x00 * x00; pq1 += x01 * x01;
            }
            if (gr0 + 8 < N_PER_DEG) {
                *(float2*)(out + (size_t)(deg_base + gr0 + 8) * OUT_C + col0) = make_float2(x10, x11);
                ps0 += x10; ps1 += x11; pq0 += x10 * x10; pq1 += x11 * x11;
            }
        }
#pragma unroll
        for (int m = 4; m < 32; m <<= 1) {
            ps0 += __shfl_xor_sync(0xffffffffu, ps0, m);
            ps1 += __shfl_xor_sync(0xffffffffu, ps1, m);
            pq0 += __shfl_xor_sync(0xffffffffu, pq0, m);
            pq1 += __shfl_xor_sync(0xffffffffu, pq1, m);
        }
        if ((lane >> 2) == 0) {
            atomicAdd(&s_sum[col0], ps0);
            atomicAdd(&s_sum[col0 + 1], ps1);
            atomicAdd(&s_sq[col0], pq0);
            atomicAdd(&s_sq[col0 + 1], pq1);
        }
    }

    __syncthreads();
    if (tid < OUT_C) {
        atomicAdd(&g_sum[tid], s_sum[tid]);
        atomicAdd(&g_sumsq[tid], s_sq[tid]);
    }
}

// ---------------- merged kernel: all 4 degrees in one launch ----------------
__global__ __launch_bounds__(512, 1)
void gconv_all(const float* __restrict__ atom_repr,
               const float* __restrict__ bond_repr,
               const int* __restrict__ a1, const int* __restrict__ a2,
               const int* __restrict__ a3, const int* __restrict__ a4,
               const int* __restrict__ b1, const int* __restrict__ b2,
               const int* __restrict__ b3, const int* __restrict__ b4,
               const float* __restrict__ W1, const float* __restrict__ W2,
               const float* __restrict__ W3, const float* __restrict__ W4,
               const float* __restrict__ Wself,
               const float* __restrict__ bias,
               float* __restrict__ out) {
    extern __shared__ char smem[];
    const int d = blockIdx.x & 3;          // interleave degrees for balance
    const int tile_base = (blockIdx.x >> 2) * TILE_M;
    switch (d) {
        case 0: gconv_body<1>(atom_repr, bond_repr, a1, b1, W1, Wself, bias, out, 0 * N_PER_DEG, tile_base, smem); break;
        case 1: gconv_body<2>(atom_repr, bond_repr, a2, b2, W2, Wself, bias, out, 1 * N_PER_DEG, tile_base, smem); break;
        case 2: gconv_body<3>(atom_repr, bond_repr, a3, b3, W3, Wself, bias, out, 2 * N_PER_DEG, tile_base, smem); break;
        default: gconv_body<4>(atom_repr, bond_repr, a4, b4, W4, Wself, bias, out, 3 * N_PER_DEG, tile_base, smem); break;
    }
}

// ---------------- K0: zero stats ----------------
__global__ void zero_stats_kernel() {
    if (threadIdx.x < OUT_C) { g_sum[threadIdx.x] = 0.f; g_sumsq[threadIdx.x] = 0.f; }
}

// ---------------- K3: finalize mean / inv-std ----------------
__global__ void finalize_stats_kernel() {
    int c = threadIdx.x;
    if (c < OUT_C) {
        float mean = g_sum[c] * (1.0f / N_ATOMS);
        float var = g_sumsq[c] * (1.0f / N_ATOMS) - mean * mean;
        g_mean[c] = mean;
        g_istd[c] = rsqrtf(var + BN_EPS);
    }
}

// ---------------- K4: BN normalize + ReLU in place ----------------
__global__ void bn_relu_kernel(float4* __restrict__ x, int n4) {
    int t = blockIdx.x * blockDim.x + threadIdx.x;
    int stride = gridDim.x * blockDim.x;   // multiple of 32
    int c = (t & 31) * 4;
    float m0 = g_mean[c + 0], m1 = g_mean[c + 1], m2 = g_mean[c + 2], m3 = g_mean[c + 3];
    float i0 = g_istd[c + 0], i1 = g_istd[c + 1], i2 = g_istd[c + 2], i3 = g_istd[c + 3];
    for (int i = t; i < n4; i += stride) {
        float4 v = x[i];
        v.x = fmaxf((v.x - m0) * i0, 0.f);
        v.y = fmaxf((v.y - m1) * i1, 0.f);
        v.z = fmaxf((v.z - m2) * i2, 0.f);
        v.w = fmaxf((v.w - m3) * i3, 0.f);
        x[i] = v;
    }
}

// ---------------- launch ----------------
extern "C" void kernel_launch(void* const* d_in, const int* in_sizes, int n_in,
                              void* d_out, int out_size) {
    (void)n_in; (void)out_size;

    const float* atom_repr = (const float*)d_in[0];
    const float* bond_repr = (const float*)d_in[1];
    const int* aidx[4];
    const int* bidx[4];
    const float* W[4];

    if (in_sizes[4] == OUT_C * (NODE + EDGE)) {
        for (int d = 0; d < 4; d++) {
            aidx[d] = (const int*)d_in[2 + 3 * d];
            bidx[d] = (const int*)d_in[3 + 3 * d];
            W[d]    = (const float*)d_in[4 + 3 * d];
        }
    } else {
        for (int d = 0; d < 4; d++) {
            aidx[d] = (const int*)d_in[2 + d];
            bidx[d] = (const int*)d_in[6 + d];
            W[d]    = (const float*)d_in[10 + d];
        }
    }
    const float* Wself = (const float*)d_in[14];
    const float* bias  = (const float*)d_in[15];
    float* out = (float*)d_out;

    cudaFuncSetAttribute(gconv_all, cudaFuncAttributeMaxDynamicSharedMemorySize, SMEM_TOTAL);

    zero_stats_kernel<<<1, 128>>>();
    gconv_all<<<4 * N_TILES, 512, SMEM_TOTAL>>>(
        atom_repr, bond_repr,
        aidx[0], aidx[1], aidx[2], aidx[3],
        bidx[0], bidx[1], bidx[2], bidx[3],
        W[0], W[1], W[2], W[3],
        Wself, bias, out);

    finalize_stats_kernel<<<1, 128>>>();
    const int n4 = (N_ATOMS * OUT_C) / 4;
    bn_relu_kernel<<<2960, 256>>>((float4*)out, n4);
}